// round 12
// baseline (speedup 1.0000x reference)
#include <cuda_runtime.h>
#include <math.h>
#include <stdint.h>

#define NN 50000
#define EE 320000
constexpr int DN   = 256;
constexpr int DEF  = 128;
constexpr int TD   = 64;
constexpr int DEIN = 192;
constexpr int H    = 8;

// ---------------- scratch ---------------------------------------------------
__device__ float g_Q[(size_t)NN * DN];
__device__ float g_K[(size_t)NN * DN];
__device__ float g_V[(size_t)NN * DN];
__device__ float g_acc[(size_t)NN * DN];
__device__ float g_denom[(size_t)NN * H];

// ---------------- helpers ---------------------------------------------------
__device__ __forceinline__ void red_add_v4(float* p, float4 v) {
    asm volatile("red.global.add.v4.f32 [%0], {%1,%2,%3,%4};"
                 :: "l"(p), "f"(v.x), "f"(v.y), "f"(v.z), "f"(v.w) : "memory");
}
__device__ __forceinline__ void red_add_f(float* p, float v) {
    asm volatile("red.global.add.f32 [%0], %1;" :: "l"(p), "f"(v) : "memory");
}
__device__ __forceinline__ uint32_t f2tf32(float f) {
    uint32_t r; asm("cvt.rna.tf32.f32 %0, %1;" : "=r"(r) : "f"(f)); return r;
}
__device__ __forceinline__ void mma_tf32(float* c, const uint32_t* a, const uint32_t* b) {
    asm volatile(
        "mma.sync.aligned.m16n8k8.row.col.f32.tf32.tf32.f32 "
        "{%0,%1,%2,%3}, {%4,%5,%6,%7}, {%8,%9}, {%0,%1,%2,%3};"
        : "+f"(c[0]), "+f"(c[1]), "+f"(c[2]), "+f"(c[3])
        : "r"(a[0]), "r"(a[1]), "r"(a[2]), "r"(a[3]), "r"(b[0]), "r"(b[1]));
}

// ---------------- smem layouts ----------------------------------------------
// node kernel (256 thr): A bufs 16KB, B bufs 16KB (BN=128)
constexpr int SM_T  = 0;
constexpr int SM_W  = 512;
constexpr int SM_BT = 768;
constexpr int SM_A0 = 1024;
constexpr int SM_A1 = SM_A0 + 16384;
constexpr int SM_B0N = SM_A1 + 16384;
constexpr int SM_B1N = SM_B0N + 16384;
constexpr int SMEM_NODE = SM_B1N + 16384;          // 66560
// edge kernel (512 thr): B bufs 32KB (BN=256)
constexpr int SM_B0E = SM_A1 + 16384;               // 33792
constexpr int SM_B1E = SM_B0E + 32768;              // 66560
constexpr int EP_STRIDE = 260;
constexpr int SMEM_EDGE_MAIN = SM_B1E + 32768;      // 99328
constexpr int SMEM_EDGE = SM_A0 + 128 * EP_STRIDE * 4;  // 134144 (> main; sEp reuse)

// XOR-swap: w[t] = v[t ^ xr]
__device__ __forceinline__ void xorswap4(float4 v, int xr,
                                         float& w0, float& w1, float& w2, float& w3) {
    w0 = v.x; w1 = v.y; w2 = v.z; w3 = v.w;
    if (xr & 1) { float t = w0; w0 = w1; w1 = t; t = w2; w2 = w3; w3 = t; }
    if (xr & 2) { float t = w0; w0 = w2; w2 = t; t = w1; w1 = w3; w3 = t; }
}

// ---- consumer-layout address helpers ----------------------------------------
// A: sA[((ks*8 + mt)*32 + ln)*4 + ri]   (128 rows x 32 kk)
__device__ __forceinline__ void putA(uint32_t* sA, int row, int kk, float v) {
    int r = row & 15, mt = row >> 4, ks = kk >> 3;
    int ln = (r & 7) * 4 + (kk & 3);
    int ri = (r >> 3) + 2 * ((kk >> 2) & 1);
    sA[((ks * 8 + mt) * 32 + ln) * 4 + ri] = f2tf32(v);
}

// ================= 256-thread staging (node kernel) ==========================
__device__ __forceinline__ int stageA_base256(int tid) {
    int R0 = tid >> 3, c4 = tid & 7;
    return (c4 >> 1) * 1024 + (R0 >> 4) * 128 + (R0 & 7) * 16
         + ((R0 >> 3) & 1) + 2 * (c4 & 1);
}
__device__ __forceinline__ void stA_store(uint32_t* sA, int base, int stepi,
                                          int i, int xr, float4 v) {
    float w0, w1, w2, w3;
    xorswap4(v, xr, w0, w1, w2, w3);
    uint32_t* p = sA + base + stepi * i;
    p[4 * (0 ^ xr)] = f2tf32(w0);
    p[4 * (1 ^ xr)] = f2tf32(w1);
    p[4 * (2 ^ xr)] = f2tf32(w2);
    p[4 * (3 ^ xr)] = f2tf32(w3);
}

__device__ __forceinline__ void stage_A_node(uint32_t* sA, const float* __restrict__ X,
                                             int m0, int k0) {
    int tid = threadIdx.x;
    int xr = (tid >> 1) & 3;
    int R0 = tid >> 3, c4 = tid & 7;
    int base = stageA_base256(tid);
#pragma unroll
    for (int i = 0; i < 4; i++) {
        int node = m0 + R0 + 32 * i;
        float4 v = make_float4(0.f, 0.f, 0.f, 0.f);
        if (node < NN) v = *(const float4*)&X[(size_t)node * DN + k0 + c4 * 4];
        stA_store(sA, base, 256, i, xr, v);
    }
}

// node B: 128 rows (half matrix), conflict-free
__device__ __forceinline__ void stage_B_node(uint32_t* sB, const float* __restrict__ W,
                                             int n0, int k0, int stride) {
    int tid = threadIdx.x;
    int xr = (tid >> 1) & 3;
    int N0 = tid >> 3, c4 = tid & 7;
    int base = (c4 >> 1) * 1024 + (N0 >> 3) * 64 + (N0 & 7) * 8 + (c4 & 1);
#pragma unroll
    for (int i = 0; i < 4; i++) {
        int n = N0 + 32 * i;
        float4 v = *(const float4*)&W[(size_t)(n0 + n) * stride + k0 + c4 * 4];
        float w0, w1, w2, w3;
        xorswap4(v, xr, w0, w1, w2, w3);
        uint32_t* p = sB + base + 256 * i;
        p[2 * (0 ^ xr)] = f2tf32(w0);
        p[2 * (1 ^ xr)] = f2tf32(w1);
        p[2 * (2 ^ xr)] = f2tf32(w2);
        p[2 * (3 ^ xr)] = f2tf32(w3);
    }
}

// ================= 512-thread staging (edge kernel) ==========================
// B full 256 rows: sB[((ks*32 + nt)*32 + ln)*2 + ri]; conflict-free
__device__ __forceinline__ void stage_B_full512(uint32_t* sB, const float* __restrict__ W,
                                                int k0, int stride) {
    int tid = threadIdx.x;
    int xr = (tid >> 1) & 3;
    int R0 = tid >> 3, c4 = tid & 7;          // R0: 0..63
    int base = (c4 >> 1) * 2048 + (R0 >> 3) * 64 + (R0 & 7) * 8 + (c4 & 1);
#pragma unroll
    for (int i = 0; i < 4; i++) {
        int n = R0 + 64 * i;
        float4 v = *(const float4*)&W[(size_t)n * stride + k0 + c4 * 4];
        float w0, w1, w2, w3;
        xorswap4(v, xr, w0, w1, w2, w3);
        uint32_t* p = sB + base + 512 * i;
        p[2 * (0 ^ xr)] = f2tf32(w0);
        p[2 * (1 ^ xr)] = f2tf32(w1);
        p[2 * (2 ^ xr)] = f2tf32(w2);
        p[2 * (3 ^ xr)] = f2tf32(w3);
    }
}

// A (ef path) with 512 threads: rows R0 + 64i (i<2); 2-way max
__device__ __forceinline__ void stage_A_ef512(uint32_t* sA, const float* __restrict__ ef,
                                              int e0, int k0) {
    int tid = threadIdx.x;
    int xr = (tid >> 1) & 3;
    int R0 = tid >> 3, c4 = tid & 7;          // R0: 0..63
    int base = (c4 >> 1) * 1024 + (R0 >> 4) * 128 + (R0 & 7) * 16
             + ((R0 >> 3) & 1) + 2 * (c4 & 1);
#pragma unroll
    for (int i = 0; i < 2; i++) {
        int row = R0 + 64 * i;                 // mt = R0>>4 + 4i -> +512i
        float4 v = *(const float4*)&ef[(size_t)(e0 + row) * DEF + k0 + c4 * 4];
        stA_store(sA, base, 512, i, xr, v);
    }
}

// cos staging, 512 threads, conflict-free bijection:
// kk = lane[2:0] | i0<<3 | wq3<<4 ; row = lane3 | i1<<1 | i2<<2 | lane4<<3 | (wq&7)<<4
__device__ __forceinline__ void stage_A_cos512(uint32_t* sA, const char* smem, int c) {
    const float* sT  = (const float*)(smem + SM_T);
    const float* sW  = (const float*)(smem + SM_W);
    const float* sBt = (const float*)(smem + SM_BT);
    int tid = threadIdx.x;
    int lane = tid & 31, wq = tid >> 5;        // wq: 0..15
    int k0 = c * 32;
#pragma unroll
    for (int i = 0; i < 8; i++) {
        int kk  = (lane & 7) | ((i & 1) << 3) | ((wq >> 3) << 4);
        int row = ((lane >> 3) & 1) | (((i >> 1) & 1) << 1) | (((i >> 2) & 1) << 2)
                | (((lane >> 4) & 1) << 3) | ((wq & 7) << 4);
        float v = cosf(sT[row] * sW[k0 + kk] + sBt[k0 + kk]);
        putA(sA, row, kk, v);
    }
}

// ---- warp-tile 32x64 chunk; B tile has NT rows of nt ----
template <int NT>
__device__ __forceinline__ void chunk_mma_t(const uint32_t* sA, const uint32_t* sB,
                                            int warpM, int warpN, int lane,
                                            float acc[2][8][4]) {
#pragma unroll
    for (int ks = 0; ks < 4; ks++) {
        uint32_t af[2][4];
#pragma unroll
        for (int m = 0; m < 2; m++)
            *(uint4*)af[m] = *(const uint4*)&sA[((ks * 8 + warpM * 2 + m) * 32 + lane) * 4];
        uint32_t bf[8][2];
#pragma unroll
        for (int j = 0; j < 8; j++)
            *(uint2*)bf[j] = *(const uint2*)&sB[((ks * NT + warpN * 8 + j) * 32 + lane) * 2];
#pragma unroll
        for (int m = 0; m < 2; m++)
#pragma unroll
            for (int j = 0; j < 8; j++) mma_tf32(acc[m][j], af[m], bf[j]);
    }
}

// ---------------- node GEMMs (unchanged from R11) ----------------------------
__global__ __launch_bounds__(256, 2)
void k_node_mma(const float* __restrict__ X,
                const float* __restrict__ Wq, const float* __restrict__ Wk,
                const float* __restrict__ Wv, const float* __restrict__ Ws,
                const float* __restrict__ bq, const float* __restrict__ bk,
                const float* __restrict__ bv, const float* __restrict__ bs,
                float* __restrict__ out) {
    extern __shared__ char smem[];
    const int tid = threadIdx.x, wid = tid >> 5, lane = tid & 31;
    const int warpM = wid & 3, warpN = wid >> 2;
    const int m0 = blockIdx.y * 128;
    const int bx = blockIdx.x, mat = bx >> 1, n0 = (bx & 1) * 128;
    const float* W; const float* bias; float* dst;
    if      (mat == 0) { W = Wq; bias = bq; dst = g_Q; }
    else if (mat == 1) { W = Wk; bias = bk; dst = g_K; }
    else if (mat == 2) { W = Wv; bias = bv; dst = g_V; }
    else               { W = Ws; bias = bs; dst = out; }

    if (bx == 4) {
        int i4 = m0 * 2 + tid;
        if (i4 < NN * H / 4)
            ((float4*)g_denom)[i4] = make_float4(0.f, 0.f, 0.f, 0.f);
    }

    uint32_t* sA[2] = { (uint32_t*)(smem + SM_A0), (uint32_t*)(smem + SM_A1) };
    uint32_t* sB[2] = { (uint32_t*)(smem + SM_B0N), (uint32_t*)(smem + SM_B1N) };

    float acc[2][8][4] = {};

    stage_A_node(sA[0], X, m0, 0);
    stage_B_node(sB[0], W, n0, 0, DN);
    __syncthreads();

    for (int c = 0; c < 8; c++) {
        chunk_mma_t<16>(sA[c & 1], sB[c & 1], warpM, warpN, lane, acc);
        if (c < 7) {
            stage_A_node(sA[(c + 1) & 1], X, m0, (c + 1) * 32);
            stage_B_node(sB[(c + 1) & 1], W, n0, (c + 1) * 32, DN);
        }
        __syncthreads();
    }

    float2 bb[8];
#pragma unroll
    for (int j = 0; j < 8; j++)
        bb[j] = *(const float2*)&bias[n0 + warpN * 64 + j * 8 + (lane & 3) * 2];
#pragma unroll
    for (int m = 0; m < 2; m++)
#pragma unroll
        for (int rv = 0; rv < 2; rv++) {
            int node = m0 + warpM * 32 + m * 16 + rv * 8 + (lane >> 2);
            if (node >= NN) continue;
            size_t off = (size_t)node * DN + n0 + warpN * 64 + (lane & 3) * 2;
            float* dp = dst + off;
#pragma unroll
            for (int j = 0; j < 8; j++) {
                float2 o = make_float2(acc[m][j][rv * 2 + 0] + bb[j].x,
                                       acc[m][j][rv * 2 + 1] + bb[j].y);
                *(float2*)(dp + j * 8) = o;
            }
            if (mat == 2) {
                float* zp = g_acc + off;
#pragma unroll
                for (int j = 0; j < 8; j++)
                    *(float2*)(zp + j * 8) = make_float2(0.f, 0.f);
            }
        }
}

// ------- edge GEMM, full-N CTA (128 edges x 256 cols), 512 threads ----------
__global__ __launch_bounds__(512, 1)
void k_edge_mma(const float* __restrict__ ef, const int* __restrict__ etup,
                const float* __restrict__ We, const float* __restrict__ times,
                const float* __restrict__ wt, const float* __restrict__ bt) {
    extern __shared__ char smem[];
    const int tid = threadIdx.x, wid = tid >> 5, lane = tid & 31;
    const int warpM = wid & 3, warpN = wid >> 2;   // 4M x 4N
    const int e0 = blockIdx.x * 128;

    if (tid < 128) ((float*)(smem + SM_T))[tid] = times[e0 + tid];
    else if (tid >= 128 && tid < 192) {
        ((float*)(smem + SM_W))[tid - 128]  = wt[tid - 128];
        ((float*)(smem + SM_BT))[tid - 128] = bt[tid - 128];
    }
    __syncthreads();

    uint32_t* sA[2] = { (uint32_t*)(smem + SM_A0), (uint32_t*)(smem + SM_A1) };
    uint32_t* sB[2] = { (uint32_t*)(smem + SM_B0E), (uint32_t*)(smem + SM_B1E) };

    float acc[2][8][4] = {};

    stage_A_cos512(sA[0], smem, 0);
    stage_B_full512(sB[0], We, 0, DEIN);
    __syncthreads();

    for (int c = 0; c < 6; c++) {
        chunk_mma_t<32>(sA[c & 1], sB[c & 1], warpM, warpN, lane, acc);
        if (c < 5) {
            if (c == 0) stage_A_cos512(sA[1], smem, 1);
            else        stage_A_ef512(sA[(c + 1) & 1], ef, e0, (c + 1) * 32 - 64);
            stage_B_full512(sB[(c + 1) & 1], We, (c + 1) * 32, DEIN);
        }
        __syncthreads();
    }

    // ---- transpose acc into smem ep tile (128 x 260) ----
    float* sEp = (float*)(smem + SM_A0);
#pragma unroll
    for (int m = 0; m < 2; m++)
#pragma unroll
        for (int rv = 0; rv < 2; rv++) {
            int row = warpM * 32 + m * 16 + rv * 8 + (lane >> 2);
            int col = warpN * 64 + (lane & 3) * 2;
#pragma unroll
            for (int j = 0; j < 8; j++)
                *(float2*)&sEp[row * EP_STRIDE + col + j * 8] =
                    make_float2(acc[m][j][rv * 2 + 0], acc[m][j][rv * 2 + 1]);
        }
    __syncthreads();

    // ---- warp-per-edge epilogue, full 256-col rows, unroll 2 ----
    const float scale = 0.17677669529663687f;
    const int hb0 = lane >> 3, hb1 = 4 + (lane >> 3);
    const int c0 = lane * 4, c1 = 128 + lane * 4;

    // lanes 0-7: src of this warp's 8 edges; lanes 16-23: dst
    int my_sd = etup[(lane >> 4) * EE + e0 + wid * 8 + (lane & 7)];

#pragma unroll
    for (int t = 0; t < 8; t += 2) {
        int el0 = wid * 8 + t, el1 = el0 + 1;
        int s0 = __shfl_sync(0xffffffffu, my_sd, t);
        int d0 = __shfl_sync(0xffffffffu, my_sd, 16 + t);
        int s1 = __shfl_sync(0xffffffffu, my_sd, t + 1);
        int d1 = __shfl_sync(0xffffffffu, my_sd, 17 + t);

        float4 eA0 = *(const float4*)&sEp[el0 * EP_STRIDE + c0];
        float4 eB0 = *(const float4*)&sEp[el0 * EP_STRIDE + c1];
        float4 eA1 = *(const float4*)&sEp[el1 * EP_STRIDE + c0];
        float4 eB1 = *(const float4*)&sEp[el1 * EP_STRIDE + c1];

        const float4 qA0 = *(const float4*)&g_Q[(size_t)d0 * DN + c0];
        const float4 qB0 = *(const float4*)&g_Q[(size_t)d0 * DN + c1];
        const float4 kA0 = *(const float4*)&g_K[(size_t)s0 * DN + c0];
        const float4 kB0 = *(const float4*)&g_K[(size_t)s0 * DN + c1];
        const float4 vA0 = *(const float4*)&g_V[(size_t)s0 * DN + c0];
        const float4 vB0 = *(const float4*)&g_V[(size_t)s0 * DN + c1];
        const float4 qA1 = *(const float4*)&g_Q[(size_t)d1 * DN + c0];
        const float4 qB1 = *(const float4*)&g_Q[(size_t)d1 * DN + c1];
        const float4 kA1 = *(const float4*)&g_K[(size_t)s1 * DN + c0];
        const float4 kB1 = *(const float4*)&g_K[(size_t)s1 * DN + c1];
        const float4 vA1 = *(const float4*)&g_V[(size_t)s1 * DN + c0];
        const float4 vB1 = *(const float4*)&g_V[(size_t)s1 * DN + c1];

        float pA0 = qA0.x * (kA0.x + eA0.x) + qA0.y * (kA0.y + eA0.y)
                  + qA0.z * (kA0.z + eA0.z) + qA0.w * (kA0.w + eA0.w);
        float pB0 = qB0.x * (kB0.x + eB0.x) + qB0.y * (kB0.y + eB0.y)
                  + qB0.z * (kB0.z + eB0.z) + qB0.w * (kB0.w + eB0.w);
        float pA1 = qA1.x * (kA1.x + eA1.x) + qA1.y * (kA1.y + eA1.y)
                  + qA1.z * (kA1.z + eA1.z) + qA1.w * (kA1.w + eA1.w);
        float pB1 = qB1.x * (kB1.x + eB1.x) + qB1.y * (kB1.y + eB1.y)
                  + qB1.z * (kB1.z + eB1.z) + qB1.w * (kB1.w + eB1.w);
#pragma unroll
        for (int m = 1; m <= 4; m <<= 1) {
            pA0 += __shfl_xor_sync(0xffffffffu, pA0, m);
            pB0 += __shfl_xor_sync(0xffffffffu, pB0, m);
            pA1 += __shfl_xor_sync(0xffffffffu, pA1, m);
            pB1 += __shfl_xor_sync(0xffffffffu, pB1, m);
        }
        float wA0 = __expf(pA0 * scale), wB0 = __expf(pB0 * scale);
        float wA1 = __expf(pA1 * scale), wB1 = __expf(pB1 * scale);

        float4 rA0 = make_float4(wA0 * (vA0.x + eA0.x), wA0 * (vA0.y + eA0.y),
                                 wA0 * (vA0.z + eA0.z), wA0 * (vA0.w + eA0.w));
        float4 rB0 = make_float4(wB0 * (vB0.x + eB0.x), wB0 * (vB0.y + eB0.y),
                                 wB0 * (vB0.z + eB0.z), wB0 * (vB0.w + eB0.w));
        float4 rA1 = make_float4(wA1 * (vA1.x + eA1.x), wA1 * (vA1.y + eA1.y),
                                 wA1 * (vA1.z + eA1.z), wA1 * (vA1.w + eA1.w));
        float4 rB1 = make_float4(wB1 * (vB1.x + eB1.x), wB1 * (vB1.y + eB1.y),
                                 wB1 * (vB1.z + eB1.z), wB1 * (vB1.w + eB1.w));
        red_add_v4(&g_acc[(size_t)d0 * DN + c0], rA0);
        red_add_v4(&g_acc[(size_t)d0 * DN + c1], rB0);
        red_add_v4(&g_acc[(size_t)d1 * DN + c0], rA1);
        red_add_v4(&g_acc[(size_t)d1 * DN + c1], rB1);
        if ((lane & 7) == 0) {
            red_add_f(&g_denom[d0 * H + hb0], wA0);
            red_add_f(&g_denom[d0 * H + hb1], wB0);
            red_add_f(&g_denom[d1 * H + hb0], wA1);
            red_add_f(&g_denom[d1 * H + hb1], wB1);
        }
    }
}

// ---------------- finalize: out = skip + acc/denom ---------------------------
__global__ __launch_bounds__(256)
void k_finalize(float* __restrict__ out) {
    int idx = blockIdx.x * blockDim.x + threadIdx.x;
    if (idx >= NN * DN / 4) return;
    int node = idx >> 6;
    int col4 = idx & 63;
    int head = col4 >> 3;
    float den = g_denom[node * H + head] + 1e-16f;
    float inv = 1.0f / den;
    float4 a = ((const float4*)g_acc)[idx];
    float4 o = ((float4*)out)[idx];
    o.x += a.x * inv; o.y += a.y * inv; o.z += a.z * inv; o.w += a.w * inv;
    ((float4*)out)[idx] = o;
}

// ---------------- launch ----------------------------------------------------
extern "C" void kernel_launch(void* const* d_in, const int* in_sizes, int n_in,
                              void* d_out, int out_size) {
    const int*   etup       = (const int*)  d_in[0];
    const float* edge_feats = (const float*)d_in[1];
    const float* times      = (const float*)d_in[2];
    const float* X          = (const float*)d_in[3];
    const float* w_time     = (const float*)d_in[4];
    const float* b_time     = (const float*)d_in[5];
    const float* Wq         = (const float*)d_in[6];
    const float* bq         = (const float*)d_in[7];
    const float* Wk         = (const float*)d_in[8];
    const float* bk         = (const float*)d_in[9];
    const float* Wv         = (const float*)d_in[10];
    const float* bv         = (const float*)d_in[11];
    const float* We         = (const float*)d_in[12];
    const float* Ws         = (const float*)d_in[13];
    const float* bs         = (const float*)d_in[14];
    float* out = (float*)d_out;

    cudaFuncSetAttribute(k_node_mma, cudaFuncAttributeMaxDynamicSharedMemorySize, SMEM_NODE);
    cudaFuncSetAttribute(k_edge_mma, cudaFuncAttributeMaxDynamicSharedMemorySize, SMEM_EDGE);

    k_node_mma<<<dim3(8, (NN + 127) / 128), 256, SMEM_NODE>>>(
        X, Wq, Wk, Wv, Ws, bq, bk, bv, bs, out);
    k_edge_mma<<<EE / 128, 512, SMEM_EDGE>>>(
        edge_feats, etup, We, times, w_time, b_time);
    k_finalize<<<(NN * DN / 4 + 255) / 256, 256>>>(out);
}

// round 13
// speedup vs baseline: 1.1203x; 1.1203x over previous
#include <cuda_runtime.h>
#include <math.h>
#include <stdint.h>

#define NN 50000
#define EE 320000
constexpr int DN   = 256;
constexpr int DEF  = 128;
constexpr int TD   = 64;
constexpr int DEIN = 192;
constexpr int H    = 8;

// ---------------- scratch ---------------------------------------------------
__device__ float g_Q[(size_t)NN * DN];
__device__ float g_K[(size_t)NN * DN];
__device__ float g_V[(size_t)NN * DN];
__device__ float g_acc[(size_t)NN * DN];
__device__ float g_denom[(size_t)NN * H];

// ---------------- helpers ---------------------------------------------------
__device__ __forceinline__ void red_add_v4(float* p, float4 v) {
    asm volatile("red.global.add.v4.f32 [%0], {%1,%2,%3,%4};"
                 :: "l"(p), "f"(v.x), "f"(v.y), "f"(v.z), "f"(v.w) : "memory");
}
__device__ __forceinline__ void red_add_f(float* p, float v) {
    asm volatile("red.global.add.f32 [%0], %1;" :: "l"(p), "f"(v) : "memory");
}
__device__ __forceinline__ uint32_t f2tf32(float f) {
    uint32_t r; asm("cvt.rna.tf32.f32 %0, %1;" : "=r"(r) : "f"(f)); return r;
}
__device__ __forceinline__ void mma_tf32(float* c, const uint32_t* a, const uint32_t* b) {
    asm volatile(
        "mma.sync.aligned.m16n8k8.row.col.f32.tf32.tf32.f32 "
        "{%0,%1,%2,%3}, {%4,%5,%6,%7}, {%8,%9}, {%0,%1,%2,%3};"
        : "+f"(c[0]), "+f"(c[1]), "+f"(c[2]), "+f"(c[3])
        : "r"(a[0]), "r"(a[1]), "r"(a[2]), "r"(a[3]), "r"(b[0]), "r"(b[1]));
}

// ---------------- smem layout -----------------------------------------------
constexpr int SM_T  = 0;
constexpr int SM_W  = 512;
constexpr int SM_BT = 768;
constexpr int SM_A0 = 1024;
constexpr int SM_A1 = SM_A0 + 16384;
constexpr int SM_B0 = SM_A1 + 16384;
constexpr int SM_B1 = SM_B0 + 16384;
constexpr int SMEM_NODE = SM_B1 + 16384;          // 66560
constexpr int EP_STRIDE = 132;
constexpr int SMEM_EDGE = SM_A0 + 128 * EP_STRIDE * 4;  // 68608

// XOR-swap: produce w[t] = v[t ^ xr]
__device__ __forceinline__ void xorswap4(float4 v, int xr,
                                         float& w0, float& w1, float& w2, float& w3) {
    w0 = v.x; w1 = v.y; w2 = v.z; w3 = v.w;
    if (xr & 1) { float t = w0; w0 = w1; w1 = t; t = w2; w2 = w3; w3 = t; }
    if (xr & 2) { float t = w0; w0 = w2; w2 = t; t = w1; w1 = w3; w3 = t; }
}

// ---- A staging: base + immediate offsets, XOR store order (2-way max) ----
__device__ __forceinline__ int stageA_base(int tid) {
    int R0 = tid >> 3, c4 = tid & 7;
    return (c4 >> 1) * 1024 + (R0 >> 4) * 128 + (R0 & 7) * 16
         + ((R0 >> 3) & 1) + 2 * (c4 & 1);
}
__device__ __forceinline__ void stA_store(uint32_t* sA, int base, int i, int xr, float4 v) {
    float w0, w1, w2, w3;
    xorswap4(v, xr, w0, w1, w2, w3);
    uint32_t* p = sA + base + 256 * i;
    p[4 * (0 ^ xr)] = f2tf32(w0);
    p[4 * (1 ^ xr)] = f2tf32(w1);
    p[4 * (2 ^ xr)] = f2tf32(w2);
    p[4 * (3 ^ xr)] = f2tf32(w3);
}

__device__ __forceinline__ void stage_A_node(uint32_t* sA, const float* __restrict__ X,
                                             int m0, int k0) {
    int tid = threadIdx.x;
    int xr = (tid >> 1) & 3;
    int R0 = tid >> 3, c4 = tid & 7;
    int base = stageA_base(tid);
#pragma unroll
    for (int i = 0; i < 4; i++) {
        int node = m0 + R0 + 32 * i;
        float4 v = make_float4(0.f, 0.f, 0.f, 0.f);
        if (node < NN) v = *(const float4*)&X[(size_t)node * DN + k0 + c4 * 4];
        stA_store(sA, base, i, xr, v);
    }
}

// ---- B staging: conflict-free ----
__device__ __forceinline__ void stage_B_w(uint32_t* sB, const float* __restrict__ W,
                                          int n0, int k0, int stride) {
    int tid = threadIdx.x;
    int xr = (tid >> 1) & 3;
    int N0 = tid >> 3, c4 = tid & 7;
    int base = (c4 >> 1) * 1024 + (N0 >> 3) * 64 + (N0 & 7) * 8 + (c4 & 1);
#pragma unroll
    for (int i = 0; i < 4; i++) {
        int n = N0 + 32 * i;
        float4 v = *(const float4*)&W[(size_t)(n0 + n) * stride + k0 + c4 * 4];
        float w0, w1, w2, w3;
        xorswap4(v, xr, w0, w1, w2, w3);
        uint32_t* p = sB + base + 256 * i;
        p[2 * (0 ^ xr)] = f2tf32(w0);
        p[2 * (1 ^ xr)] = f2tf32(w1);
        p[2 * (2 ^ xr)] = f2tf32(w2);
        p[2 * (3 ^ xr)] = f2tf32(w3);
    }
}

// ---- edge A staging: cos path with conflict-free bijective mapping ----
__device__ __forceinline__ void stage_A_edge(uint32_t* sA, const char* smem,
                                             const float* __restrict__ ef,
                                             int e0, int c) {
    int tid = threadIdx.x;
    if (c < 2) {
        const float* sT  = (const float*)(smem + SM_T);
        const float* sW  = (const float*)(smem + SM_W);
        const float* sBt = (const float*)(smem + SM_BT);
        int lane = tid & 31, wq = tid >> 5;
        int k0 = c * 32;
        int base = wq * 128 + ((lane >> 4) & 1) * 16 + (lane & 3) * 4
                 + ((lane >> 3) & 1) + 2 * ((lane >> 2) & 1);
        int rowb = ((lane >> 4) & 1) | (((lane >> 3) & 1) << 3) | (wq << 4);
        int kkb  = lane & 7;
#pragma unroll
        for (int i = 0; i < 16; i++) {
            int kk  = kkb | ((i & 3) << 3);
            int row = rowb | (((i >> 2) & 3) << 1);
            int addr = base + (i & 3) * 1024 + ((i >> 2) & 3) * 32;
            // __cosf: RRO+MUFU; abs err ~1e-6 << tf32 quantization (2^-11)
            float v = __cosf(sT[row] * sW[k0 + kk] + sBt[k0 + kk]);
            sA[addr] = f2tf32(v);
        }
    } else {
        int k0 = c * 32 - 64;
        int xr = (tid >> 1) & 3;
        int R0 = tid >> 3, c4 = tid & 7;
        int base = stageA_base(tid);
#pragma unroll
        for (int i = 0; i < 4; i++) {
            int row = R0 + 32 * i;
            float4 v = *(const float4*)&ef[(size_t)(e0 + row) * DEF + k0 + c4 * 4];
            stA_store(sA, base, i, xr, v);
        }
    }
}

__device__ __forceinline__ void chunk_mma(const uint32_t* sA, const uint32_t* sB,
                                          int warpM, int warpN, int lane,
                                          float acc[2][8][4]) {
#pragma unroll
    for (int ks = 0; ks < 4; ks++) {
        uint32_t af[2][4];
#pragma unroll
        for (int m = 0; m < 2; m++)
            *(uint4*)af[m] = *(const uint4*)&sA[((ks * 8 + warpM * 2 + m) * 32 + lane) * 4];
        uint32_t bf[8][2];
#pragma unroll
        for (int j = 0; j < 8; j++)
            *(uint2*)bf[j] = *(const uint2*)&sB[((ks * 16 + warpN * 8 + j) * 32 + lane) * 2];
#pragma unroll
        for (int m = 0; m < 2; m++)
#pragma unroll
            for (int j = 0; j < 8; j++) mma_tf32(acc[m][j], af[m], bf[j]);
    }
}

// ---------------- node GEMMs: Q,K,V,skip (folds g_acc + g_denom zeroing) -----
__global__ __launch_bounds__(256, 2)
void k_node_mma(const float* __restrict__ X,
                const float* __restrict__ Wq, const float* __restrict__ Wk,
                const float* __restrict__ Wv, const float* __restrict__ Ws,
                const float* __restrict__ bq, const float* __restrict__ bk,
                const float* __restrict__ bv, const float* __restrict__ bs,
                float* __restrict__ out) {
    extern __shared__ char smem[];
    const int tid = threadIdx.x, wid = tid >> 5, lane = tid & 31;
    const int warpM = wid & 3, warpN = wid >> 2;
    const int m0 = blockIdx.y * 128;
    const int bx = blockIdx.x, mat = bx >> 1, n0 = (bx & 1) * 128;
    const float* W; const float* bias; float* dst;
    if      (mat == 0) { W = Wq; bias = bq; dst = g_Q; }
    else if (mat == 1) { W = Wk; bias = bk; dst = g_K; }
    else if (mat == 2) { W = Wv; bias = bv; dst = g_V; }
    else               { W = Ws; bias = bs; dst = out; }

    if (bx == 4) {
        int i4 = m0 * 2 + tid;
        if (i4 < NN * H / 4)
            ((float4*)g_denom)[i4] = make_float4(0.f, 0.f, 0.f, 0.f);
    }

    uint32_t* sA[2] = { (uint32_t*)(smem + SM_A0), (uint32_t*)(smem + SM_A1) };
    uint32_t* sB[2] = { (uint32_t*)(smem + SM_B0), (uint32_t*)(smem + SM_B1) };

    float acc[2][8][4] = {};

    stage_A_node(sA[0], X, m0, 0);
    stage_B_w(sB[0], W, n0, 0, DN);
    __syncthreads();

    for (int c = 0; c < 8; c++) {
        chunk_mma(sA[c & 1], sB[c & 1], warpM, warpN, lane, acc);
        if (c < 7) {
            stage_A_node(sA[(c + 1) & 1], X, m0, (c + 1) * 32);
            stage_B_w(sB[(c + 1) & 1], W, n0, (c + 1) * 32, DN);
        }
        __syncthreads();
    }

    float2 bb[8];
#pragma unroll
    for (int j = 0; j < 8; j++)
        bb[j] = *(const float2*)&bias[n0 + warpN * 64 + j * 8 + (lane & 3) * 2];
#pragma unroll
    for (int m = 0; m < 2; m++)
#pragma unroll
        for (int rv = 0; rv < 2; rv++) {
            int node = m0 + warpM * 32 + m * 16 + rv * 8 + (lane >> 2);
            if (node >= NN) continue;
            size_t off = (size_t)node * DN + n0 + warpN * 64 + (lane & 3) * 2;
            float* dp = dst + off;
#pragma unroll
            for (int j = 0; j < 8; j++) {
                float2 o = make_float2(acc[m][j][rv * 2 + 0] + bb[j].x,
                                       acc[m][j][rv * 2 + 1] + bb[j].y);
                *(float2*)(dp + j * 8) = o;
            }
            if (mat == 2) {
                float* zp = g_acc + off;
#pragma unroll
                for (int j = 0; j < 8; j++)
                    *(float2*)(zp + j * 8) = make_float2(0.f, 0.f);
            }
        }
}

// ------- edge GEMM + fused time-enc + alpha + exp + scatter-aggregate -------
__global__ __launch_bounds__(256, 2)
void k_edge_mma(const float* __restrict__ ef, const int* __restrict__ etup,
                const float* __restrict__ We, const float* __restrict__ times,
                const float* __restrict__ wt, const float* __restrict__ bt) {
    extern __shared__ char smem[];
    const int tid = threadIdx.x, wid = tid >> 5, lane = tid & 31;
    const int warpM = wid & 3, warpN = wid >> 2;
    const int e0 = blockIdx.y * 128;
    const int n0 = blockIdx.x * 128;

    if (tid < 128) ((float*)(smem + SM_T))[tid] = times[e0 + tid];
    if (tid < 64) {
        ((float*)(smem + SM_W))[tid]  = wt[tid];
        ((float*)(smem + SM_BT))[tid] = bt[tid];
    }
    __syncthreads();

    uint32_t* sA[2] = { (uint32_t*)(smem + SM_A0), (uint32_t*)(smem + SM_A1) };
    uint32_t* sB[2] = { (uint32_t*)(smem + SM_B0), (uint32_t*)(smem + SM_B1) };

    float acc[2][8][4] = {};

    stage_A_edge(sA[0], smem, ef, e0, 0);
    stage_B_w(sB[0], We, n0, 0, DEIN);
    __syncthreads();

    for (int c = 0; c < 6; c++) {
        chunk_mma(sA[c & 1], sB[c & 1], warpM, warpN, lane, acc);
        if (c < 5) {
            stage_A_edge(sA[(c + 1) & 1], smem, ef, e0, c + 1);
            stage_B_w(sB[(c + 1) & 1], We, n0, (c + 1) * 32, DEIN);
        }
        __syncthreads();
    }

    // ---- transpose acc fragments into smem ep tile ----
    float* sEp = (float*)(smem + SM_A0);
#pragma unroll
    for (int m = 0; m < 2; m++)
#pragma unroll
        for (int rv = 0; rv < 2; rv++) {
            int row = warpM * 32 + m * 16 + rv * 8 + (lane >> 2);
            int col = warpN * 64 + (lane & 3) * 2;
#pragma unroll
            for (int j = 0; j < 8; j++)
                *(float2*)&sEp[row * EP_STRIDE + col + j * 8] =
                    make_float2(acc[m][j][rv * 2 + 0], acc[m][j][rv * 2 + 1]);
        }
    __syncthreads();

    // ---- warp-per-edge epilogue, unroll 4 for deep gather MLP ----
    const float scale = 0.17677669529663687f;
    const int hb = (n0 >> 5) + (lane >> 3);
    const int colg = n0 + lane * 4;

    int my_sd = etup[(lane >> 4) * EE + e0 + wid * 16 + (lane & 15)];

#pragma unroll
    for (int t = 0; t < 16; t += 4) {
        int s[4], d[4];
#pragma unroll
        for (int u = 0; u < 4; u++) {
            s[u] = __shfl_sync(0xffffffffu, my_sd, t + u);
            d[u] = __shfl_sync(0xffffffffu, my_sd, 16 + t + u);
        }
        float4 ep[4], qv[4], kv[4], vv[4];
#pragma unroll
        for (int u = 0; u < 4; u++) {
            int eloc = wid * 16 + t + u;
            ep[u] = *(const float4*)&sEp[eloc * EP_STRIDE + lane * 4];
            qv[u] = *(const float4*)&g_Q[(size_t)d[u] * DN + colg];
            kv[u] = *(const float4*)&g_K[(size_t)s[u] * DN + colg];
            vv[u] = *(const float4*)&g_V[(size_t)s[u] * DN + colg];
        }
        float p[4];
#pragma unroll
        for (int u = 0; u < 4; u++)
            p[u] = qv[u].x * (kv[u].x + ep[u].x) + qv[u].y * (kv[u].y + ep[u].y)
                 + qv[u].z * (kv[u].z + ep[u].z) + qv[u].w * (kv[u].w + ep[u].w);
#pragma unroll
        for (int m = 1; m <= 4; m <<= 1)
#pragma unroll
            for (int u = 0; u < 4; u++)
                p[u] += __shfl_xor_sync(0xffffffffu, p[u], m);
#pragma unroll
        for (int u = 0; u < 4; u++) {
            float wgt = __expf(p[u] * scale);
            float4 r = make_float4(wgt * (vv[u].x + ep[u].x),
                                   wgt * (vv[u].y + ep[u].y),
                                   wgt * (vv[u].z + ep[u].z),
                                   wgt * (vv[u].w + ep[u].w));
            red_add_v4(&g_acc[(size_t)d[u] * DN + colg], r);
            if ((lane & 7) == 0) red_add_f(&g_denom[d[u] * H + hb], wgt);
        }
    }
}

// ---------------- finalize: out = skip + acc/denom ---------------------------
__global__ __launch_bounds__(256)
void k_finalize(float* __restrict__ out) {
    int idx = blockIdx.x * blockDim.x + threadIdx.x;
    if (idx >= NN * DN / 4) return;
    int node = idx >> 6;
    int col4 = idx & 63;
    int head = col4 >> 3;
    float den = g_denom[node * H + head] + 1e-16f;
    float inv = 1.0f / den;
    float4 a = ((const float4*)g_acc)[idx];
    float4 o = ((float4*)out)[idx];
    o.x += a.x * inv; o.y += a.y * inv; o.z += a.z * inv; o.w += a.w * inv;
    ((float4*)out)[idx] = o;
}

// ---------------- launch ----------------------------------------------------
extern "C" void kernel_launch(void* const* d_in, const int* in_sizes, int n_in,
                              void* d_out, int out_size) {
    const int*   etup       = (const int*)  d_in[0];
    const float* edge_feats = (const float*)d_in[1];
    const float* times      = (const float*)d_in[2];
    const float* X          = (const float*)d_in[3];
    const float* w_time     = (const float*)d_in[4];
    const float* b_time     = (const float*)d_in[5];
    const float* Wq         = (const float*)d_in[6];
    const float* bq         = (const float*)d_in[7];
    const float* Wk         = (const float*)d_in[8];
    const float* bk         = (const float*)d_in[9];
    const float* Wv         = (const float*)d_in[10];
    const float* bv         = (const float*)d_in[11];
    const float* We         = (const float*)d_in[12];
    const float* Ws         = (const float*)d_in[13];
    const float* bs         = (const float*)d_in[14];
    float* out = (float*)d_out;

    cudaFuncSetAttribute(k_node_mma, cudaFuncAttributeMaxDynamicSharedMemorySize, SMEM_NODE);
    cudaFuncSetAttribute(k_edge_mma, cudaFuncAttributeMaxDynamicSharedMemorySize, SMEM_EDGE);

    k_node_mma<<<dim3(8, (NN + 127) / 128), 256, SMEM_NODE>>>(
        X, Wq, Wk, Wv, Ws, bq, bk, bv, bs, out);
    k_edge_mma<<<dim3(2, EE / 128), 256, SMEM_EDGE>>>(
        edge_feats, etup, We, times, w_time, b_time);
    k_finalize<<<(NN * DN / 4 + 255) / 256, 256>>>(out);
}

// round 14
// speedup vs baseline: 1.3697x; 1.2227x over previous
#include <cuda_runtime.h>
#include <cuda_fp16.h>
#include <math.h>
#include <stdint.h>

#define NN 50000
#define EE 320000
constexpr int DN   = 256;
constexpr int DEF  = 128;
constexpr int TD   = 64;
constexpr int DEIN = 192;
constexpr int H    = 8;

// ---------------- scratch ---------------------------------------------------
__device__ float g_Q[(size_t)NN * DN];
__device__ float g_K[(size_t)NN * DN];
__device__ float g_V[(size_t)NN * DN];
__device__ float g_acc[(size_t)NN * DN];
__device__ float g_denom[(size_t)NN * H];

// ---------------- helpers ---------------------------------------------------
__device__ __forceinline__ void red_add_v4(float* p, float4 v) {
    asm volatile("red.global.add.v4.f32 [%0], {%1,%2,%3,%4};"
                 :: "l"(p), "f"(v.x), "f"(v.y), "f"(v.z), "f"(v.w) : "memory");
}
__device__ __forceinline__ void red_add_f(float* p, float v) {
    asm volatile("red.global.add.f32 [%0], %1;" :: "l"(p), "f"(v) : "memory");
}
__device__ __forceinline__ uint32_t pack2(float lo, float hi) {
    __half2 h = __floats2half2_rn(lo, hi);
    return *(uint32_t*)&h;
}
// fp16 mma: D(16x8,f32) += A(16x16,f16) * B(16x8,f16)
__device__ __forceinline__ void mma_f16(float* c, const uint32_t* a, const uint32_t* b) {
    asm volatile(
        "mma.sync.aligned.m16n8k16.row.col.f32.f16.f16.f32 "
        "{%0,%1,%2,%3}, {%4,%5,%6,%7}, {%8,%9}, {%0,%1,%2,%3};"
        : "+f"(c[0]), "+f"(c[1]), "+f"(c[2]), "+f"(c[3])
        : "r"(a[0]), "r"(a[1]), "r"(a[2]), "r"(a[3]), "r"(b[0]), "r"(b[1]));
}

// ---------------- smem layout -----------------------------------------------
// A bufs 8KB (128x32 fp16), B bufs 8KB (128x32 fp16)
constexpr int SM_T  = 0;
constexpr int SM_W  = 512;
constexpr int SM_BT = 768;
constexpr int SM_A0 = 1024;
constexpr int SM_A1 = SM_A0 + 8192;
constexpr int SM_B0 = SM_A1 + 8192;
constexpr int SM_B1 = SM_B0 + 8192;
constexpr int SMEM_NODE = SM_B1 + 8192;           // 33792
constexpr int EP_STRIDE = 132;
constexpr int SMEM_EDGE = SM_A0 + 128 * EP_STRIDE * 4;  // 68608

// ---- fp16 fragment smem layouts ---------------------------------------------
// A: sA[((ks*8 + mt)*32 + ln)*4 + ri]   ks<2 (K=16 each), uint32 = fp16x2 kpair
//    reg ri at lane ln -> row = mt*16 + (ln>>2) + (ri&1)*8,
//                         kpair = (ln&3) + (ri>>1)*4   (k = ks*16 + kpair*2 +{0,1})
// B: sB[((ks*16 + nt)*32 + ln)*2 + ri]  -> n = nt*8 + (ln>>2), kpair = (ln&3)+ri*4

// A staging: thread (R0=tid>>3, c4=tid&7) loads float4 at (row=R0+32i, k=c4*4..+3)
//   -> ks=c4>>2, kpairs p0=(c4&3)*2, p0+1; addr step 4 per kpair.
//   XOR store order on xc=ks: bank = 16*t3 + 8*c0 + 4*(s^c2) + 2*c1 -> 2-way max.
__device__ __forceinline__ void stA_f16(uint32_t* sA, int i, float4 v) {
    int tid = threadIdx.x;
    int R0 = tid >> 3, c4 = tid & 7;
    int ks = c4 >> 2, c03 = c4 & 3;
    int r = R0 & 15;
    int mt = (R0 >> 4) + 2 * i;
    int base = ((ks * 8 + mt) * 32 + (r & 7) * 4 + 2 * (c03 & 1)) * 4
             + (r >> 3) + 2 * (c03 >> 1);
    uint32_t h0 = pack2(v.x, v.y);   // kpair p0
    uint32_t h1 = pack2(v.z, v.w);   // kpair p0+1
    uint32_t* p = sA + base;
    int xc = ks;
    p[4 * xc]       = xc ? h1 : h0;
    p[4 - 4 * xc]   = xc ? h0 : h1;
}

__device__ __forceinline__ void stage_A_node(uint32_t* sA, const float* __restrict__ X,
                                             int m0, int k0) {
    int tid = threadIdx.x;
    int R0 = tid >> 3, c4 = tid & 7;
#pragma unroll
    for (int i = 0; i < 4; i++) {
        int node = m0 + R0 + 32 * i;
        float4 v = make_float4(0.f, 0.f, 0.f, 0.f);
        if (node < NN) v = *(const float4*)&X[(size_t)node * DN + k0 + c4 * 4];
        stA_f16(sA, i, v);
    }
}

// B staging: conflict-free (bank = 8*(t4t3) + 4*c0 + 2*(s^c2) + c1, all 5 bits)
__device__ __forceinline__ void stage_B_w(uint32_t* sB, const float* __restrict__ W,
                                          int n0, int k0, int stride) {
    int tid = threadIdx.x;
    int N0 = tid >> 3, c4 = tid & 7;
    int ks = c4 >> 2, c03 = c4 & 3;
#pragma unroll
    for (int i = 0; i < 4; i++) {
        int n = N0 + 32 * i;
        float4 v = *(const float4*)&W[(size_t)(n0 + n) * stride + k0 + c4 * 4];
        int nt = n >> 3;
        int base = ((ks * 16 + nt) * 32 + (n & 7) * 4 + 2 * (c03 & 1)) * 2
                 + (c03 >> 1);
        uint32_t h0 = pack2(v.x, v.y);
        uint32_t h1 = pack2(v.z, v.w);
        uint32_t* p = sB + base;
        int xc = ks;
        p[2 * xc]     = xc ? h1 : h0;
        p[2 - 2 * xc] = xc ? h0 : h1;
    }
}

// ---- edge A staging: cos path (conflict-free bijection) + ef path ----
__device__ __forceinline__ void stage_A_edge(uint32_t* sA, const char* smem,
                                             const float* __restrict__ ef,
                                             int e0, int c) {
    int tid = threadIdx.x;
    if (c < 2) {
        const float* sT  = (const float*)(smem + SM_T);
        const float* sW  = (const float*)(smem + SM_W);
        const float* sBt = (const float*)(smem + SM_BT);
        int lane = tid & 31, wq = tid >> 5;
        int k0 = c * 32;
        int p = lane & 7;
        int r0 = (lane >> 3) & 1, r3 = (lane >> 4) & 1;
        int mt = wq;
#pragma unroll
        for (int i = 0; i < 8; i++) {
            int ks = i >> 2;
            int r = r0 | ((i & 3) << 1) | (r3 << 3);
            int row = r | (mt << 4);
            int kk = k0 + (ks * 8 + p) * 2;
            float t = sT[row];
            float v0 = __cosf(t * sW[kk]     + sBt[kk]);
            float v1 = __cosf(t * sW[kk + 1] + sBt[kk + 1]);
            int addr = ((ks * 8 + mt) * 32 + (r & 7) * 4 + (p & 3)) * 4
                     + (r >> 3) + 2 * ((p >> 2) & 1);
            sA[addr] = pack2(v0, v1);
        }
    } else {
        int k0 = c * 32 - 64;
        int R0 = tid >> 3, c4 = tid & 7;
#pragma unroll
        for (int i = 0; i < 4; i++) {
            int row = R0 + 32 * i;
            float4 v = *(const float4*)&ef[(size_t)(e0 + row) * DEF + k0 + c4 * 4];
            stA_f16(sA, i, v);
        }
    }
}

// ---- warp-tile 32x64 chunk (K=32 = 2 fp16 mma steps) ----
__device__ __forceinline__ void chunk_mma(const uint32_t* sA, const uint32_t* sB,
                                          int warpM, int warpN, int lane,
                                          float acc[2][8][4]) {
#pragma unroll
    for (int ks = 0; ks < 2; ks++) {
        uint32_t af[2][4];
#pragma unroll
        for (int m = 0; m < 2; m++)
            *(uint4*)af[m] = *(const uint4*)&sA[((ks * 8 + warpM * 2 + m) * 32 + lane) * 4];
        uint32_t bf[8][2];
#pragma unroll
        for (int j = 0; j < 8; j++)
            *(uint2*)bf[j] = *(const uint2*)&sB[((ks * 16 + warpN * 8 + j) * 32 + lane) * 2];
#pragma unroll
        for (int m = 0; m < 2; m++)
#pragma unroll
            for (int j = 0; j < 8; j++) mma_f16(acc[m][j], af[m], bf[j]);
    }
}

// ---------------- node GEMMs: Q,K,V,skip (folds g_acc + g_denom zeroing) -----
__global__ __launch_bounds__(256, 2)
void k_node_mma(const float* __restrict__ X,
                const float* __restrict__ Wq, const float* __restrict__ Wk,
                const float* __restrict__ Wv, const float* __restrict__ Ws,
                const float* __restrict__ bq, const float* __restrict__ bk,
                const float* __restrict__ bv, const float* __restrict__ bs,
                float* __restrict__ out) {
    extern __shared__ char smem[];
    const int tid = threadIdx.x, wid = tid >> 5, lane = tid & 31;
    const int warpM = wid & 3, warpN = wid >> 2;
    const int m0 = blockIdx.y * 128;
    const int bx = blockIdx.x, mat = bx >> 1, n0 = (bx & 1) * 128;
    const float* W; const float* bias; float* dst;
    if      (mat == 0) { W = Wq; bias = bq; dst = g_Q; }
    else if (mat == 1) { W = Wk; bias = bk; dst = g_K; }
    else if (mat == 2) { W = Wv; bias = bv; dst = g_V; }
    else               { W = Ws; bias = bs; dst = out; }

    if (bx == 4) {
        int i4 = m0 * 2 + tid;
        if (i4 < NN * H / 4)
            ((float4*)g_denom)[i4] = make_float4(0.f, 0.f, 0.f, 0.f);
    }

    uint32_t* sA[2] = { (uint32_t*)(smem + SM_A0), (uint32_t*)(smem + SM_A1) };
    uint32_t* sB[2] = { (uint32_t*)(smem + SM_B0), (uint32_t*)(smem + SM_B1) };

    float acc[2][8][4] = {};

    stage_A_node(sA[0], X, m0, 0);
    stage_B_w(sB[0], W, n0, 0, DN);
    __syncthreads();

    for (int c = 0; c < 8; c++) {
        chunk_mma(sA[c & 1], sB[c & 1], warpM, warpN, lane, acc);
        if (c < 7) {
            stage_A_node(sA[(c + 1) & 1], X, m0, (c + 1) * 32);
            stage_B_w(sB[(c + 1) & 1], W, n0, (c + 1) * 32, DN);
        }
        __syncthreads();
    }

    float2 bb[8];
#pragma unroll
    for (int j = 0; j < 8; j++)
        bb[j] = *(const float2*)&bias[n0 + warpN * 64 + j * 8 + (lane & 3) * 2];
#pragma unroll
    for (int m = 0; m < 2; m++)
#pragma unroll
        for (int rv = 0; rv < 2; rv++) {
            int node = m0 + warpM * 32 + m * 16 + rv * 8 + (lane >> 2);
            if (node >= NN) continue;
            size_t off = (size_t)node * DN + n0 + warpN * 64 + (lane & 3) * 2;
            float* dp = dst + off;
#pragma unroll
            for (int j = 0; j < 8; j++) {
                float2 o = make_float2(acc[m][j][rv * 2 + 0] + bb[j].x,
                                       acc[m][j][rv * 2 + 1] + bb[j].y);
                *(float2*)(dp + j * 8) = o;
            }
            if (mat == 2) {
                float* zp = g_acc + off;
#pragma unroll
                for (int j = 0; j < 8; j++)
                    *(float2*)(zp + j * 8) = make_float2(0.f, 0.f);
            }
        }
}

// ------- edge GEMM + fused time-enc + alpha + exp + scatter-aggregate -------
__global__ __launch_bounds__(256, 2)
void k_edge_mma(const float* __restrict__ ef, const int* __restrict__ etup,
                const float* __restrict__ We, const float* __restrict__ times,
                const float* __restrict__ wt, const float* __restrict__ bt) {
    extern __shared__ char smem[];
    const int tid = threadIdx.x, wid = tid >> 5, lane = tid & 31;
    const int warpM = wid & 3, warpN = wid >> 2;
    const int e0 = blockIdx.y * 128;
    const int n0 = blockIdx.x * 128;

    if (tid < 128) ((float*)(smem + SM_T))[tid] = times[e0 + tid];
    if (tid < 64) {
        ((float*)(smem + SM_W))[tid]  = wt[tid];
        ((float*)(smem + SM_BT))[tid] = bt[tid];
    }
    __syncthreads();

    uint32_t* sA[2] = { (uint32_t*)(smem + SM_A0), (uint32_t*)(smem + SM_A1) };
    uint32_t* sB[2] = { (uint32_t*)(smem + SM_B0), (uint32_t*)(smem + SM_B1) };

    float acc[2][8][4] = {};

    stage_A_edge(sA[0], smem, ef, e0, 0);
    stage_B_w(sB[0], We, n0, 0, DEIN);
    __syncthreads();

    for (int c = 0; c < 6; c++) {
        chunk_mma(sA[c & 1], sB[c & 1], warpM, warpN, lane, acc);
        if (c < 5) {
            stage_A_edge(sA[(c + 1) & 1], smem, ef, e0, c + 1);
            stage_B_w(sB[(c + 1) & 1], We, n0, (c + 1) * 32, DEIN);
        }
        __syncthreads();
    }

    // ---- transpose acc fragments into smem ep tile ----
    float* sEp = (float*)(smem + SM_A0);
#pragma unroll
    for (int m = 0; m < 2; m++)
#pragma unroll
        for (int rv = 0; rv < 2; rv++) {
            int row = warpM * 32 + m * 16 + rv * 8 + (lane >> 2);
            int col = warpN * 64 + (lane & 3) * 2;
#pragma unroll
            for (int j = 0; j < 8; j++)
                *(float2*)&sEp[row * EP_STRIDE + col + j * 8] =
                    make_float2(acc[m][j][rv * 2 + 0], acc[m][j][rv * 2 + 1]);
        }
    __syncthreads();

    // ---- warp-per-edge epilogue, unroll 4 for deep gather MLP ----
    const float scale = 0.17677669529663687f;
    const int hb = (n0 >> 5) + (lane >> 3);
    const int colg = n0 + lane * 4;

    int my_sd = etup[(lane >> 4) * EE + e0 + wid * 16 + (lane & 15)];

#pragma unroll
    for (int t = 0; t < 16; t += 4) {
        int s[4], d[4];
#pragma unroll
        for (int u = 0; u < 4; u++) {
            s[u] = __shfl_sync(0xffffffffu, my_sd, t + u);
            d[u] = __shfl_sync(0xffffffffu, my_sd, 16 + t + u);
        }
        float4 ep[4], qv[4], kv[4], vv[4];
#pragma unroll
        for (int u = 0; u < 4; u++) {
            int eloc = wid * 16 + t + u;
            ep[u] = *(const float4*)&sEp[eloc * EP_STRIDE + lane * 4];
            qv[u] = *(const float4*)&g_Q[(size_t)d[u] * DN + colg];
            kv[u] = *(const float4*)&g_K[(size_t)s[u] * DN + colg];
            vv[u] = *(const float4*)&g_V[(size_t)s[u] * DN + colg];
        }
        float p[4];
#pragma unroll
        for (int u = 0; u < 4; u++)
            p[u] = qv[u].x * (kv[u].x + ep[u].x) + qv[u].y * (kv[u].y + ep[u].y)
                 + qv[u].z * (kv[u].z + ep[u].z) + qv[u].w * (kv[u].w + ep[u].w);
#pragma unroll
        for (int m = 1; m <= 4; m <<= 1)
#pragma unroll
            for (int u = 0; u < 4; u++)
                p[u] += __shfl_xor_sync(0xffffffffu, p[u], m);
#pragma unroll
        for (int u = 0; u < 4; u++) {
            float wgt = __expf(p[u] * scale);
            float4 r = make_float4(wgt * (vv[u].x + ep[u].x),
                                   wgt * (vv[u].y + ep[u].y),
                                   wgt * (vv[u].z + ep[u].z),
                                   wgt * (vv[u].w + ep[u].w));
            red_add_v4(&g_acc[(size_t)d[u] * DN + colg], r);
            if ((lane & 7) == 0) red_add_f(&g_denom[d[u] * H + hb], wgt);
        }
    }
}

// ---------------- finalize: out = skip + acc/denom ---------------------------
__global__ __launch_bounds__(256)
void k_finalize(float* __restrict__ out) {
    int idx = blockIdx.x * blockDim.x + threadIdx.x;
    if (idx >= NN * DN / 4) return;
    int node = idx >> 6;
    int col4 = idx & 63;
    int head = col4 >> 3;
    float den = g_denom[node * H + head] + 1e-16f;
    float inv = 1.0f / den;
    float4 a = ((const float4*)g_acc)[idx];
    float4 o = ((float4*)out)[idx];
    o.x += a.x * inv; o.y += a.y * inv; o.z += a.z * inv; o.w += a.w * inv;
    ((float4*)out)[idx] = o;
}

// ---------------- launch ----------------------------------------------------
extern "C" void kernel_launch(void* const* d_in, const int* in_sizes, int n_in,
                              void* d_out, int out_size) {
    const int*   etup       = (const int*)  d_in[0];
    const float* edge_feats = (const float*)d_in[1];
    const float* times      = (const float*)d_in[2];
    const float* X          = (const float*)d_in[3];
    const float* w_time     = (const float*)d_in[4];
    const float* b_time     = (const float*)d_in[5];
    const float* Wq         = (const float*)d_in[6];
    const float* bq         = (const float*)d_in[7];
    const float* Wk         = (const float*)d_in[8];
    const float* bk         = (const float*)d_in[9];
    const float* Wv         = (const float*)d_in[10];
    const float* bv         = (const float*)d_in[11];
    const float* We         = (const float*)d_in[12];
    const float* Ws         = (const float*)d_in[13];
    const float* bs         = (const float*)d_in[14];
    float* out = (float*)d_out;

    cudaFuncSetAttribute(k_node_mma, cudaFuncAttributeMaxDynamicSharedMemorySize, SMEM_NODE);
    cudaFuncSetAttribute(k_edge_mma, cudaFuncAttributeMaxDynamicSharedMemorySize, SMEM_EDGE);

    k_node_mma<<<dim3(8, (NN + 127) / 128), 256, SMEM_NODE>>>(
        X, Wq, Wk, Wv, Ws, bq, bk, bv, bs, out);
    k_edge_mma<<<dim3(2, EE / 128), 256, SMEM_EDGE>>>(
        edge_feats, etup, We, times, w_time, b_time);
    k_finalize<<<(NN * DN / 4 + 255) / 256, 256>>>(out);
}